// round 6
// baseline (speedup 1.0000x reference)
#include <cuda_runtime.h>
#include <cuda_bf16.h>
#include <math.h>

// Problem constants
#define TT 1024
#define BB 64
#define DD 512
#define HH 512
#define KK 1024            // D + H
#define GG 2048            // 4*H
#define EPSV 1e-5f
#define MM (TT * BB)       // 65536
#define OUT_HC_OFF (TT * BB * HH)
#define NBLK 64
#define THR 256
#define WST 520            // smem halfword stride (conflict-free for ldmatrix)

// Scratch (device globals — no runtime allocation allowed)
__device__ float g_xw[(size_t)MM * GG];                  // 512 MB
__device__ __nv_bfloat16 g_xhi[(size_t)MM * DD];
__device__ __nv_bfloat16 g_xlo[(size_t)MM * DD];
__device__ __nv_bfloat16 g_whi[(size_t)GG * KK];         // W^T [n][k]
__device__ __nv_bfloat16 g_wlo[(size_t)GG * KK];
__device__ __nv_bfloat16 g_hhi[BB * HH];
__device__ __nv_bfloat16 g_hlo[BB * HH];
__device__ float g_c0[BB * HH];
__device__ float g_gates[BB * GG];                        // full gates per step
__device__ unsigned g_flags[NBLK * 8];                    // barrier flags, 32B apart

__device__ __forceinline__ void split2(float v, __nv_bfloat16& hi, __nv_bfloat16& lo) {
    hi = __float2bfloat16(v);
    lo = __float2bfloat16(v - __bfloat162float(hi));
}

__device__ __forceinline__ void mma_bf16(float* d, const unsigned* a, const unsigned* b) {
    asm volatile(
        "mma.sync.aligned.m16n8k16.row.col.f32.bf16.bf16.f32 "
        "{%0,%1,%2,%3}, {%4,%5,%6,%7}, {%8,%9}, {%0,%1,%2,%3};\n"
        : "+f"(d[0]), "+f"(d[1]), "+f"(d[2]), "+f"(d[3])
        : "r"(a[0]), "r"(a[1]), "r"(a[2]), "r"(a[3]), "r"(b[0]), "r"(b[1]));
}

__device__ __forceinline__ void ldsm_x4(unsigned* r, const void* p) {
    unsigned addr = (unsigned)__cvta_generic_to_shared(p);
    asm volatile("ldmatrix.sync.aligned.m8n8.x4.shared.b16 {%0,%1,%2,%3}, [%4];"
        : "=r"(r[0]), "=r"(r[1]), "=r"(r[2]), "=r"(r[3]) : "r"(addr));
}

__device__ __forceinline__ void st_release(unsigned* p, unsigned v) {
    asm volatile("st.release.gpu.u32 [%0], %1;" :: "l"(p), "r"(v) : "memory");
}
__device__ __forceinline__ unsigned ld_acquire(unsigned* p) {
    unsigned v;
    asm volatile("ld.acquire.gpu.u32 %0, [%1];" : "=r"(v) : "l"(p) : "memory");
    return v;
}

// flag barrier: per-block flag store (no atomic serialization), 64 pollers
__device__ __forceinline__ void bar_arrive(int blk, unsigned val) {
    __syncthreads();                       // all block work done & stores issued
    if (threadIdx.x == 0) st_release(&g_flags[blk * 8], val);
}
__device__ __forceinline__ void bar_wait(unsigned val) {
    if (threadIdx.x < NBLK) {
        while (ld_acquire(&g_flags[threadIdx.x * 8]) < val) { }
    }
    __syncthreads();
}

__device__ __forceinline__ float fast_sig(float x) {
    return __fdividef(1.f, 1.f + __expf(-x));
}
__device__ __forceinline__ float fast_tanh(float x) {
    return __fdividef(2.f, 1.f + __expf(-2.f * x)) - 1.f;
}

// ---------------------------------------------------------------------------
__global__ void init_kernel(const float* __restrict__ h0,
                            const float* __restrict__ c0) {
    int i = blockIdx.x * blockDim.x + threadIdx.x;
    if (i < NBLK * 8) g_flags[i] = 0;
    if (i < BB * HH) {
        split2(h0[i], g_hhi[i], g_hlo[i]);
        g_c0[i] = c0[i];
    }
}

__global__ void split_w_kernel(const float* __restrict__ w) {
    int idx = blockIdx.x * blockDim.x + threadIdx.x;
    if (idx < KK * GG) {
        int k = idx / GG;
        int n = idx % GG;
        __nv_bfloat16 hi, lo;
        split2(w[idx], hi, lo);
        g_whi[(size_t)n * KK + k] = hi;
        g_wlo[(size_t)n * KK + k] = lo;
    }
}

__global__ void split_x_kernel(const float* __restrict__ x) {
    size_t idx = (size_t)blockIdx.x * blockDim.x + threadIdx.x;
    if (idx < (size_t)MM * DD) {
        split2(x[idx], g_xhi[idx], g_xlo[idx]);
    }
}

// ---------------------------------------------------------------------------
// XW = X @ Wx + bias via bf16-split HMMA.  M=65536, N=2048, K=512.
// ---------------------------------------------------------------------------
__global__ void __launch_bounds__(256, 1) gemm_x_kernel(const float* __restrict__ bias) {
    __shared__ __nv_bfloat16 Ah[128][40], Al[128][40], Bh[128][40], Bl[128][40];

    const int bn = blockIdx.x * 128;
    const int bm = blockIdx.y * 128;
    const int tid = threadIdx.x;
    const int wid = tid >> 5, lane = tid & 31;
    const int wm = wid & 1, wn = wid >> 1;
    const int lr = lane >> 2, lc = lane & 3;

    float acc[4][4][4];
#pragma unroll
    for (int i = 0; i < 4; i++)
#pragma unroll
        for (int j = 0; j < 4; j++)
#pragma unroll
            for (int q = 0; q < 4; q++) acc[i][j][q] = 0.f;

    const int ldr = tid >> 1;
    const int ldc = (tid & 1) * 16;

    for (int k0 = 0; k0 < DD; k0 += 32) {
        const uint4* s;
        s = (const uint4*)&g_xhi[(size_t)(bm + ldr) * DD + k0 + ldc];
        *(uint4*)&Ah[ldr][ldc] = s[0];  *(uint4*)&Ah[ldr][ldc + 8] = s[1];
        s = (const uint4*)&g_xlo[(size_t)(bm + ldr) * DD + k0 + ldc];
        *(uint4*)&Al[ldr][ldc] = s[0];  *(uint4*)&Al[ldr][ldc + 8] = s[1];
        s = (const uint4*)&g_whi[(size_t)(bn + ldr) * KK + k0 + ldc];
        *(uint4*)&Bh[ldr][ldc] = s[0];  *(uint4*)&Bh[ldr][ldc + 8] = s[1];
        s = (const uint4*)&g_wlo[(size_t)(bn + ldr) * KK + k0 + ldc];
        *(uint4*)&Bl[ldr][ldc] = s[0];  *(uint4*)&Bl[ldr][ldc + 8] = s[1];
        __syncthreads();

#pragma unroll
        for (int ks = 0; ks < 32; ks += 16) {
            unsigned ahi[4][4], alo[4][4], bhi[4][2], blo[4][2];
#pragma unroll
            for (int im = 0; im < 4; im++) {
                int r = wm * 64 + im * 16 + lr;
                ahi[im][0] = *(const unsigned*)&Ah[r][ks + lc * 2];
                ahi[im][1] = *(const unsigned*)&Ah[r + 8][ks + lc * 2];
                ahi[im][2] = *(const unsigned*)&Ah[r][ks + 8 + lc * 2];
                ahi[im][3] = *(const unsigned*)&Ah[r + 8][ks + 8 + lc * 2];
                alo[im][0] = *(const unsigned*)&Al[r][ks + lc * 2];
                alo[im][1] = *(const unsigned*)&Al[r + 8][ks + lc * 2];
                alo[im][2] = *(const unsigned*)&Al[r][ks + 8 + lc * 2];
                alo[im][3] = *(const unsigned*)&Al[r + 8][ks + 8 + lc * 2];
            }
#pragma unroll
            for (int in = 0; in < 4; in++) {
                int n = wn * 32 + in * 8 + lr;
                bhi[in][0] = *(const unsigned*)&Bh[n][ks + lc * 2];
                bhi[in][1] = *(const unsigned*)&Bh[n][ks + 8 + lc * 2];
                blo[in][0] = *(const unsigned*)&Bl[n][ks + lc * 2];
                blo[in][1] = *(const unsigned*)&Bl[n][ks + 8 + lc * 2];
            }
#pragma unroll
            for (int im = 0; im < 4; im++)
#pragma unroll
                for (int in = 0; in < 4; in++) {
                    mma_bf16(acc[im][in], ahi[im], bhi[in]);
                    mma_bf16(acc[im][in], alo[im], bhi[in]);
                    mma_bf16(acc[im][in], ahi[im], blo[in]);
                }
        }
        __syncthreads();
    }

#pragma unroll
    for (int im = 0; im < 4; im++)
#pragma unroll
        for (int in = 0; in < 4; in++) {
            int row = bm + wm * 64 + im * 16 + lr;
            int col = bn + wn * 32 + in * 8 + lc * 2;
            float b0 = bias[col], b1 = bias[col + 1];
            float2 v;
            v.x = acc[im][in][0] + b0; v.y = acc[im][in][1] + b1;
            *(float2*)&g_xw[(size_t)row * GG + col] = v;
            v.x = acc[im][in][2] + b0; v.y = acc[im][in][3] + b1;
            *(float2*)&g_xw[(size_t)(row + 8) * GG + col] = v;
        }
}

// ---------------------------------------------------------------------------
__device__ __forceinline__ void block_reduce2(float& s, float& sq, float* shm) {
    __syncthreads();
    int lane = threadIdx.x & 31;
    int wid = threadIdx.x >> 5;
#pragma unroll
    for (int o = 16; o > 0; o >>= 1) {
        s  += __shfl_down_sync(0xffffffffu, s, o);
        sq += __shfl_down_sync(0xffffffffu, sq, o);
    }
    if (lane == 0) { shm[wid] = s; shm[8 + wid] = sq; }
    __syncthreads();
    if (threadIdx.x == 0) {
        float a = 0.f, b = 0.f;
#pragma unroll
        for (int i = 0; i < 8; i++) { a += shm[i]; b += shm[8 + i]; }
        shm[0] = a; shm[8] = b;
    }
    __syncthreads();
    s = shm[0];
    sq = shm[8];
}

// ---------------------------------------------------------------------------
// Persistent recurrence: 64 blocks x 256 threads (8 warps = 4m x 2n).
// Phase 1: block j computes FULL gate columns [32j,32j+32) (K=512) + xw slice.
// Phase 2: block b computes LN+activations for batch row b from g_gates only.
// Barriers: per-block release flags, monotonic values (no atomic contention).
// ---------------------------------------------------------------------------
__global__ void __launch_bounds__(THR, 1) lstm_persist(
        const float* __restrict__ gg, const float* __restrict__ gb,
        const float* __restrict__ cgam, const float* __restrict__ cbet,
        float* __restrict__ out) {
    extern __shared__ unsigned char sm8[];
    __nv_bfloat16* Whs = (__nv_bfloat16*)sm8;        // [32][WST]
    __nv_bfloat16* Wls = Whs + 32 * WST;
    __nv_bfloat16* Ahs = Wls + 32 * WST;             // [64][WST]
    __nv_bfloat16* Als = Ahs + 64 * WST;
    float* red = (float*)(Als + 64 * WST);           // [16]

    const int blk = blockIdx.x;
    const int tid = threadIdx.x;
    const int wid = tid >> 5, lane = tid & 31;
    const int wm = wid & 3, wn = wid >> 2;           // 4m x 2n
    const int lr = lane >> 2, lc = lane & 3;

    const int jb = blk * 32;                          // n-slice base

    // one-time: resident W^T tile [32 n][512 k] hi/lo
    // 8 threads per row, 64 halfwords (8 uint4) per thread
    {
        int r = tid >> 3;                 // 0..31
        int seg = (tid & 7) * 64;         // halfword offset
        const uint4* s = (const uint4*)&g_whi[(size_t)(jb + r) * KK + DD + seg];
        uint4* d = (uint4*)&Whs[r * WST + seg];
#pragma unroll
        for (int i = 0; i < 8; i++) d[i] = s[i];
        s = (const uint4*)&g_wlo[(size_t)(jb + r) * KK + DD + seg];
        d = (uint4*)&Wls[r * WST + seg];
#pragma unroll
        for (int i = 0; i < 8; i++) d[i] = s[i];
    }

    // ldmatrix lane addressing
    const int a_g = lane >> 3;
    const int a_row_off = (a_g & 1) * 8 + (lane & 7);
    const int a_col_off = (a_g >> 1) * 8;
    const int b_row_off = (lane & 7) + ((lane >> 4) & 1) * 8;
    const int b_col_off = ((lane >> 3) & 1) * 8;

    // phase-1 output coordinates (per thread)
    const int p1_r0 = wm * 16 + lr;                   // batch rows r0, r0+8
    const int p1_c0 = jb + wn * 16 + lc * 2;          // in=0 col
    const int p1_c1 = p1_c0 + 8;                      // in=1 col

    // phase-2 constants: block owns batch row b = blk; elements e0=tid, e1=tid+256
    const int b = blk;
    const float gf0 = gg[tid],            bf0 = gb[tid];
    const float gi0 = gg[HH + tid],       bi0 = gb[HH + tid];
    const float gg0 = gg[2 * HH + tid],   bg0 = gb[2 * HH + tid];
    const float go0 = gg[3 * HH + tid],   bo0 = gb[3 * HH + tid];
    const float gf1 = gg[tid + 256],          bf1 = gb[tid + 256];
    const float gi1 = gg[HH + tid + 256],     bi1 = gb[HH + tid + 256];
    const float gg1 = gg[2 * HH + tid + 256], bg1 = gb[2 * HH + tid + 256];
    const float go1 = gg[3 * HH + tid + 256], bo1 = gb[3 * HH + tid + 256];
    const float cga0 = cgam[tid], cbe0 = cbet[tid];
    const float cga1 = cgam[tid + 256], cbe1 = cbet[tid + 256];

    float creg0 = g_c0[b * HH + tid];
    float creg1 = g_c0[b * HH + tid + 256];
    float hl0 = 0.f, hl1 = 0.f;

    // xw prefetch registers for step t (4 float2 per thread)
    float2 xw0a, xw0b, xw1a, xw1b;
    {
        size_t base0 = (size_t)p1_r0 * GG;
        xw0a = __ldcg((const float2*)&g_xw[base0 + p1_c0]);
        xw1a = __ldcg((const float2*)&g_xw[base0 + p1_c1]);
        size_t base1 = (size_t)(p1_r0 + 8) * GG;
        xw0b = __ldcg((const float2*)&g_xw[base1 + p1_c0]);
        xw1b = __ldcg((const float2*)&g_xw[base1 + p1_c1]);
    }

    for (int t = 0; t < TT; t++) {
        // ----- phase 1: load full h (64x512 hi/lo) into smem -----
        // 4 threads per row, 128 halfwords (16 uint4) per thread
        {
            int r = tid >> 2;                 // 0..63
            int seg = (tid & 3) * 128;
            const uint4* s = (const uint4*)&g_hhi[r * HH + seg];
            uint4* d = (uint4*)&Ahs[r * WST + seg];
#pragma unroll
            for (int i = 0; i < 16; i++) d[i] = __ldcg(s + i);
            s = (const uint4*)&g_hlo[r * HH + seg];
            d = (uint4*)&Als[r * WST + seg];
#pragma unroll
            for (int i = 0; i < 16; i++) d[i] = __ldcg(s + i);
        }
        __syncthreads();

        float acc[2][4];
#pragma unroll
        for (int i = 0; i < 2; i++)
#pragma unroll
            for (int q = 0; q < 4; q++) acc[i][q] = 0.f;

        const __nv_bfloat16* Abase_h = &Ahs[(wm * 16 + a_row_off) * WST + a_col_off];
        const __nv_bfloat16* Abase_l = &Als[(wm * 16 + a_row_off) * WST + a_col_off];
        const __nv_bfloat16* Bbase_h = &Whs[(wn * 16 + b_row_off) * WST + b_col_off];
        const __nv_bfloat16* Bbase_l = &Wls[(wn * 16 + b_row_off) * WST + b_col_off];

#pragma unroll 8
        for (int ks = 0; ks < 512; ks += 16) {
            unsigned ah[4], al[4], bh[4], bl[4];
            ldsm_x4(ah, Abase_h + ks);
            ldsm_x4(al, Abase_l + ks);
            ldsm_x4(bh, Bbase_h + ks);
            ldsm_x4(bl, Bbase_l + ks);
#pragma unroll
            for (int in = 0; in < 2; in++) {
                mma_bf16(acc[in], ah, &bh[2 * in]);
                mma_bf16(acc[in], al, &bh[2 * in]);
                mma_bf16(acc[in], ah, &bl[2 * in]);
            }
        }

        // store gates slice (+ xw)
        {
            float2 v;
            v.x = acc[0][0] + xw0a.x; v.y = acc[0][1] + xw0a.y;
            *(float2*)&g_gates[p1_r0 * GG + p1_c0] = v;
            v.x = acc[0][2] + xw0b.x; v.y = acc[0][3] + xw0b.y;
            *(float2*)&g_gates[(p1_r0 + 8) * GG + p1_c0] = v;
            v.x = acc[1][0] + xw1a.x; v.y = acc[1][1] + xw1a.y;
            *(float2*)&g_gates[p1_r0 * GG + p1_c1] = v;
            v.x = acc[1][2] + xw1b.x; v.y = acc[1][3] + xw1b.y;
            *(float2*)&g_gates[(p1_r0 + 8) * GG + p1_c1] = v;
        }

        unsigned valA = 2u * t + 1u;
        bar_arrive(blk, valA);
        bar_wait(valA);

        // ----- phase 2: batch row b -----
        {
            const float* gr = g_gates + b * GG;
            float vf0 = __ldcg(&gr[tid]);
            float vi0 = __ldcg(&gr[HH + tid]);
            float vg0 = __ldcg(&gr[2 * HH + tid]);
            float vo0 = __ldcg(&gr[3 * HH + tid]);
            float vf1 = __ldcg(&gr[tid + 256]);
            float vi1 = __ldcg(&gr[HH + tid + 256]);
            float vg1 = __ldcg(&gr[2 * HH + tid + 256]);
            float vo1 = __ldcg(&gr[3 * HH + tid + 256]);

            float s = vf0 + vi0 + vg0 + vo0 + vf1 + vi1 + vg1 + vo1;
            float sq = vf0 * vf0 + vi0 * vi0 + vg0 * vg0 + vo0 * vo0
                     + vf1 * vf1 + vi1 * vi1 + vg1 * vg1 + vo1 * vo1;
            block_reduce2(s, sq, red);
            float mean = s * (1.f / GG);
            float var = sq * (1.f / GG) - mean * mean;
            float rstd = rsqrtf(var + EPSV);

            float f0 = fast_sig((vf0 - mean) * rstd * gf0 + bf0);
            float i0 = fast_sig((vi0 - mean) * rstd * gi0 + bi0);
            float q0 = fast_tanh((vg0 - mean) * rstd * gg0 + bg0);
            float o0 = fast_sig((vo0 - mean) * rstd * go0 + bo0);
            float f1 = fast_sig((vf1 - mean) * rstd * gf1 + bf1);
            float i1 = fast_sig((vi1 - mean) * rstd * gi1 + bi1);
            float q1 = fast_tanh((vg1 - mean) * rstd * gg1 + bg1);
            float o1 = fast_sig((vo1 - mean) * rstd * go1 + bo1);

            float c0 = f0 * creg0 + i0 * q0;
            float c1 = f1 * creg1 + i1 * q1;

            float s2 = c0 + c1, sq2 = c0 * c0 + c1 * c1;
            block_reduce2(s2, sq2, red);
            float mean2 = s2 * (1.f / HH);
            float var2 = sq2 * (1.f / HH) - mean2 * mean2;
            float rstd2 = rsqrtf(var2 + EPSV);

            float cn0 = (c0 - mean2) * rstd2 * cga0 + cbe0;
            float cn1 = (c1 - mean2) * rstd2 * cga1 + cbe1;
            float hn0 = o0 * fast_tanh(cn0);
            float hn1 = o1 * fast_tanh(cn1);
            creg0 = cn0; creg1 = cn1;
            hl0 = hn0; hl1 = hn1;

            __nv_bfloat16 hi, lo;
            split2(hn0, hi, lo);
            g_hhi[b * HH + tid] = hi;
            g_hlo[b * HH + tid] = lo;
            split2(hn1, hi, lo);
            g_hhi[b * HH + tid + 256] = hi;
            g_hlo[b * HH + tid + 256] = lo;
            out[((size_t)t * BB + b) * HH + tid] = hn0;
            out[((size_t)t * BB + b) * HH + tid + 256] = hn1;
        }

        unsigned valB = 2u * t + 2u;
        bar_arrive(blk, valB);

        // overlap: prefetch next step's xw slice while waiting
        if (t + 1 < TT) {
            size_t tb = (size_t)(t + 1) * BB;
            size_t base0 = (tb + p1_r0) * GG;
            xw0a = __ldcg((const float2*)&g_xw[base0 + p1_c0]);
            xw1a = __ldcg((const float2*)&g_xw[base0 + p1_c1]);
            size_t base1 = (tb + p1_r0 + 8) * GG;
            xw0b = __ldcg((const float2*)&g_xw[base1 + p1_c0]);
            xw1b = __ldcg((const float2*)&g_xw[base1 + p1_c1]);
        }
        bar_wait(valB);
    }

    out[OUT_HC_OFF + b * HH + tid] = hl0;
    out[OUT_HC_OFF + b * HH + tid + 256] = hl1;
    out[OUT_HC_OFF + BB * HH + b * HH + tid] = creg0;
    out[OUT_HC_OFF + BB * HH + b * HH + tid + 256] = creg1;
}

// ---------------------------------------------------------------------------
extern "C" void kernel_launch(void* const* d_in, const int* in_sizes, int n_in,
                              void* d_out, int out_size) {
    const float* x    = (const float*)d_in[0];
    const float* h0   = (const float*)d_in[1];
    const float* c0   = (const float*)d_in[2];
    const float* w    = (const float*)d_in[3];
    const float* bias = (const float*)d_in[4];
    const float* gg   = (const float*)d_in[5];
    const float* gb   = (const float*)d_in[6];
    const float* cg   = (const float*)d_in[7];
    const float* cb   = (const float*)d_in[8];
    float* out = (float*)d_out;

    // smem: (2*32 + 2*64) * WST * 2B + red
    const int smem_bytes = (2 * 32 + 2 * 64) * WST * 2 + 128;

    static bool attr_set = false;
    if (!attr_set) {
        cudaFuncSetAttribute(lstm_persist,
                             cudaFuncAttributeMaxDynamicSharedMemorySize, smem_bytes);
        attr_set = true;
    }

    init_kernel<<<128, 256>>>(h0, c0);
    split_w_kernel<<<(KK * GG + 255) / 256, 256>>>(w);
    split_x_kernel<<<(int)(((size_t)MM * DD + 255) / 256), 256>>>(x);

    // XW = X @ Wx + bias : M=65536, N=2048, K=512
    gemm_x_kernel<<<dim3(GG / 128, MM / 128), 256>>>(bias);

    // persistent recurrence: all 1024 steps in one launch
    lstm_persist<<<NBLK, THR, smem_bytes>>>(gg, gb, cg, cb, out);
}

// round 7
// speedup vs baseline: 1.8642x; 1.8642x over previous
#include <cuda_runtime.h>
#include <cuda_bf16.h>
#include <math.h>

// Problem constants
#define TT 1024
#define BB 64
#define DD 512
#define HH 512
#define KK 1024            // D + H
#define GG 2048            // 4*H
#define EPSV 1e-5f
#define MM (TT * BB)       // 65536
#define OUT_HC_OFF (TT * BB * HH)
#define NBLK 128           // persistent blocks (<= 148 SMs)
#define WRT 64             // writer blocks (phase 2)
#define THR 512
#define WST 264            // smem halfword stride (odd 16B multiple -> conflict-free)

// Scratch (device globals — no runtime allocation allowed)
__device__ float g_xw[(size_t)MM * GG];                  // 512 MB
__device__ __nv_bfloat16 g_xhi[(size_t)MM * DD];
__device__ __nv_bfloat16 g_xlo[(size_t)MM * DD];
__device__ __nv_bfloat16 g_whi[(size_t)GG * KK];         // W^T [n][k]
__device__ __nv_bfloat16 g_wlo[(size_t)GG * KK];
__device__ __nv_bfloat16 g_hhi[BB * HH];
__device__ __nv_bfloat16 g_hlo[BB * HH];
__device__ float g_c0[BB * HH];
__device__ float g_part[2 * BB * GG];                     // 2 K-halves of gates
__device__ unsigned g_flags[NBLK * 8];                    // barrier flags, 32B apart

__device__ __forceinline__ void split2(float v, __nv_bfloat16& hi, __nv_bfloat16& lo) {
    hi = __float2bfloat16(v);
    lo = __float2bfloat16(v - __bfloat162float(hi));
}

__device__ __forceinline__ void mma_bf16(float* d, const unsigned* a, const unsigned* b) {
    asm volatile(
        "mma.sync.aligned.m16n8k16.row.col.f32.bf16.bf16.f32 "
        "{%0,%1,%2,%3}, {%4,%5,%6,%7}, {%8,%9}, {%0,%1,%2,%3};\n"
        : "+f"(d[0]), "+f"(d[1]), "+f"(d[2]), "+f"(d[3])
        : "r"(a[0]), "r"(a[1]), "r"(a[2]), "r"(a[3]), "r"(b[0]), "r"(b[1]));
}

__device__ __forceinline__ void ldsm_x4(unsigned* r, const void* p) {
    unsigned addr = (unsigned)__cvta_generic_to_shared(p);
    asm volatile("ldmatrix.sync.aligned.m8n8.x4.shared.b16 {%0,%1,%2,%3}, [%4];"
        : "=r"(r[0]), "=r"(r[1]), "=r"(r[2]), "=r"(r[3]) : "r"(addr));
}
__device__ __forceinline__ void ldsm_x2(unsigned* r, const void* p) {
    unsigned addr = (unsigned)__cvta_generic_to_shared(p);
    asm volatile("ldmatrix.sync.aligned.m8n8.x2.shared.b16 {%0,%1}, [%2];"
        : "=r"(r[0]), "=r"(r[1]) : "r"(addr));
}

__device__ __forceinline__ void st_release(unsigned* p, unsigned v) {
    asm volatile("st.release.gpu.u32 [%0], %1;" :: "l"(p), "r"(v) : "memory");
}
__device__ __forceinline__ unsigned ld_acquire(unsigned* p) {
    unsigned v;
    asm volatile("ld.acquire.gpu.u32 %0, [%1];" : "=r"(v) : "l"(p) : "memory");
    return v;
}

// flag barrier pieces
__device__ __forceinline__ void bar_arrive(int blk, unsigned val) {
    __syncthreads();                       // all block stores issued before flag
    if (threadIdx.x == 0) st_release(&g_flags[blk * 8], val);
}
__device__ __forceinline__ void bar_wait_all(unsigned val) {   // all 128 blocks
    if (threadIdx.x < NBLK) {
        while (ld_acquire(&g_flags[threadIdx.x * 8]) < val) { }
    }
    __syncthreads();
}
__device__ __forceinline__ void bar_wait_writers(unsigned val) { // blocks 0..63
    if (threadIdx.x < WRT) {
        while (ld_acquire(&g_flags[threadIdx.x * 8]) < val) { }
    }
    __syncthreads();
}

__device__ __forceinline__ float fast_sig(float x) {
    return __fdividef(1.f, 1.f + __expf(-x));
}
__device__ __forceinline__ float fast_tanh(float x) {
    return __fdividef(2.f, 1.f + __expf(-2.f * x)) - 1.f;
}

// ---------------------------------------------------------------------------
__global__ void init_kernel(const float* __restrict__ h0,
                            const float* __restrict__ c0) {
    int i = blockIdx.x * blockDim.x + threadIdx.x;
    if (i < NBLK * 8) g_flags[i] = 0;
    if (i < BB * HH) {
        split2(h0[i], g_hhi[i], g_hlo[i]);
        g_c0[i] = c0[i];
    }
}

__global__ void split_w_kernel(const float* __restrict__ w) {
    int idx = blockIdx.x * blockDim.x + threadIdx.x;
    if (idx < KK * GG) {
        int k = idx / GG;
        int n = idx % GG;
        __nv_bfloat16 hi, lo;
        split2(w[idx], hi, lo);
        g_whi[(size_t)n * KK + k] = hi;
        g_wlo[(size_t)n * KK + k] = lo;
    }
}

__global__ void split_x_kernel(const float* __restrict__ x) {
    size_t idx = (size_t)blockIdx.x * blockDim.x + threadIdx.x;
    if (idx < (size_t)MM * DD) {
        split2(x[idx], g_xhi[idx], g_xlo[idx]);
    }
}

// ---------------------------------------------------------------------------
// XW = X @ Wx + bias via bf16-split HMMA.  M=65536, N=2048, K=512.
// (unchanged from round 3/4 — verified)
// ---------------------------------------------------------------------------
__global__ void __launch_bounds__(256, 1) gemm_x_kernel(const float* __restrict__ bias) {
    __shared__ __nv_bfloat16 Ah[128][40], Al[128][40], Bh[128][40], Bl[128][40];

    const int bn = blockIdx.x * 128;
    const int bm = blockIdx.y * 128;
    const int tid = threadIdx.x;
    const int wid = tid >> 5, lane = tid & 31;
    const int wm = wid & 1, wn = wid >> 1;
    const int lr = lane >> 2, lc = lane & 3;

    float acc[4][4][4];
#pragma unroll
    for (int i = 0; i < 4; i++)
#pragma unroll
        for (int j = 0; j < 4; j++)
#pragma unroll
            for (int q = 0; q < 4; q++) acc[i][j][q] = 0.f;

    const int ldr = tid >> 1;
    const int ldc = (tid & 1) * 16;

    for (int k0 = 0; k0 < DD; k0 += 32) {
        const uint4* s;
        s = (const uint4*)&g_xhi[(size_t)(bm + ldr) * DD + k0 + ldc];
        *(uint4*)&Ah[ldr][ldc] = s[0];  *(uint4*)&Ah[ldr][ldc + 8] = s[1];
        s = (const uint4*)&g_xlo[(size_t)(bm + ldr) * DD + k0 + ldc];
        *(uint4*)&Al[ldr][ldc] = s[0];  *(uint4*)&Al[ldr][ldc + 8] = s[1];
        s = (const uint4*)&g_whi[(size_t)(bn + ldr) * KK + k0 + ldc];
        *(uint4*)&Bh[ldr][ldc] = s[0];  *(uint4*)&Bh[ldr][ldc + 8] = s[1];
        s = (const uint4*)&g_wlo[(size_t)(bn + ldr) * KK + k0 + ldc];
        *(uint4*)&Bl[ldr][ldc] = s[0];  *(uint4*)&Bl[ldr][ldc + 8] = s[1];
        __syncthreads();

#pragma unroll
        for (int ks = 0; ks < 32; ks += 16) {
            unsigned ahi[4][4], alo[4][4], bhi[4][2], blo[4][2];
#pragma unroll
            for (int im = 0; im < 4; im++) {
                int r = wm * 64 + im * 16 + lr;
                ahi[im][0] = *(const unsigned*)&Ah[r][ks + lc * 2];
                ahi[im][1] = *(const unsigned*)&Ah[r + 8][ks + lc * 2];
                ahi[im][2] = *(const unsigned*)&Ah[r][ks + 8 + lc * 2];
                ahi[im][3] = *(const unsigned*)&Ah[r + 8][ks + 8 + lc * 2];
                alo[im][0] = *(const unsigned*)&Al[r][ks + lc * 2];
                alo[im][1] = *(const unsigned*)&Al[r + 8][ks + lc * 2];
                alo[im][2] = *(const unsigned*)&Al[r][ks + 8 + lc * 2];
                alo[im][3] = *(const unsigned*)&Al[r + 8][ks + 8 + lc * 2];
            }
#pragma unroll
            for (int in = 0; in < 4; in++) {
                int n = wn * 32 + in * 8 + lr;
                bhi[in][0] = *(const unsigned*)&Bh[n][ks + lc * 2];
                bhi[in][1] = *(const unsigned*)&Bh[n][ks + 8 + lc * 2];
                blo[in][0] = *(const unsigned*)&Bl[n][ks + lc * 2];
                blo[in][1] = *(const unsigned*)&Bl[n][ks + 8 + lc * 2];
            }
#pragma unroll
            for (int im = 0; im < 4; im++)
#pragma unroll
                for (int in = 0; in < 4; in++) {
                    mma_bf16(acc[im][in], ahi[im], bhi[in]);
                    mma_bf16(acc[im][in], alo[im], bhi[in]);
                    mma_bf16(acc[im][in], ahi[im], blo[in]);
                }
        }
        __syncthreads();
    }

#pragma unroll
    for (int im = 0; im < 4; im++)
#pragma unroll
        for (int in = 0; in < 4; in++) {
            int row = bm + wm * 64 + im * 16 + lr;
            int col = bn + wn * 32 + in * 8 + lc * 2;
            float b0 = bias[col], b1 = bias[col + 1];
            float2 v;
            v.x = acc[im][in][0] + b0; v.y = acc[im][in][1] + b1;
            *(float2*)&g_xw[(size_t)row * GG + col] = v;
            v.x = acc[im][in][2] + b0; v.y = acc[im][in][3] + b1;
            *(float2*)&g_xw[(size_t)(row + 8) * GG + col] = v;
        }
}

// ---------------------------------------------------------------------------
__device__ __forceinline__ void block_reduce2(float& s, float& sq, float* shm) {
    __syncthreads();
    int lane = threadIdx.x & 31;
    int wid = threadIdx.x >> 5;
#pragma unroll
    for (int o = 16; o > 0; o >>= 1) {
        s  += __shfl_down_sync(0xffffffffu, s, o);
        sq += __shfl_down_sync(0xffffffffu, sq, o);
    }
    if (lane == 0) { shm[wid] = s; shm[16 + wid] = sq; }
    __syncthreads();
    if (threadIdx.x == 0) {
        float a = 0.f, b = 0.f;
#pragma unroll
        for (int i = 0; i < 16; i++) { a += shm[i]; b += shm[16 + i]; }
        shm[0] = a; shm[16] = b;
    }
    __syncthreads();
    s = shm[0];
    sq = shm[16];
}

// ---------------------------------------------------------------------------
// Persistent recurrence: 128 blocks x 512 threads (16 warps = 4m x 4n).
// Block = (jn = blk & 63 -> N cols [32jn, 32jn+32), kc = blk >> 6 -> K half).
// Phase 1: partial GEMM for its (N-slice, K-half); kc=0 blocks fold in xw.
// Phase 2: blocks 0..63 (== kc 0): LN + activations for batch row b = blk.
// Barriers: flag array; non-writers skip wait-A; wait-B polls writers only.
// ---------------------------------------------------------------------------
__global__ void __launch_bounds__(THR, 1) lstm_persist(
        const float* __restrict__ gg, const float* __restrict__ gb,
        const float* __restrict__ cgam, const float* __restrict__ cbet,
        float* __restrict__ out) {
    extern __shared__ unsigned char sm8[];
    __nv_bfloat16* Whs = (__nv_bfloat16*)sm8;        // [32][WST]
    __nv_bfloat16* Wls = Whs + 32 * WST;
    __nv_bfloat16* Ahs = Wls + 32 * WST;             // [64][WST]
    __nv_bfloat16* Als = Ahs + 64 * WST;
    float* red = (float*)(Als + 64 * WST);           // [32]

    const int blk = blockIdx.x;
    const int tid = threadIdx.x;
    const int wid = tid >> 5, lane = tid & 31;
    const int wm = wid & 3, wn = wid >> 2;           // 4m x 4n
    const int lr = lane >> 2, lc = lane & 3;

    const int jn = blk & 63;
    const int kc = blk >> 6;                          // 0 or 1
    const int jb = jn * 32;                           // N-col base
    const int k0 = kc * 256;                          // K base within Wh
    const bool writer = (blk < WRT);

    // one-time: resident W^T tile [32 n][256 k] hi/lo
    // 16 threads/row x 16 halfwords (2 uint4) each
    {
        int r = tid >> 4;                 // 0..31
        int seg = (tid & 15) * 16;
        const uint4* s = (const uint4*)&g_whi[(size_t)(jb + r) * KK + DD + k0 + seg];
        uint4* d = (uint4*)&Whs[r * WST + seg];
        d[0] = s[0]; d[1] = s[1];
        s = (const uint4*)&g_wlo[(size_t)(jb + r) * KK + DD + k0 + seg];
        d = (uint4*)&Wls[r * WST + seg];
        d[0] = s[0]; d[1] = s[1];
    }

    // ldmatrix lane addressing (round-3/4-verified)
    const int a_g = lane >> 3;
    const int a_row_off = (a_g & 1) * 8 + (lane & 7);
    const int a_col_off = (a_g >> 1) * 8;
    const int b_row_off = lane & 7;
    const int b_col_off = ((lane >> 3) & 1) * 8;

    // phase-1 output coordinates
    const int p1_r = wm * 16 + lr;                    // batch rows p1_r, p1_r+8
    const int p1_c = jb + wn * 8 + lc * 2;            // gate cols c, c+1

    // phase-2 constants (writers only; b = blk)
    const int b = blk;
    float gf = 0.f, bf = 0.f, gi = 0.f, bi = 0.f, gq = 0.f, bq = 0.f,
          go = 0.f, bo = 0.f, cga = 0.f, cbe = 0.f, creg = 0.f;
    if (writer) {
        gf = gg[tid];            bf = gb[tid];
        gi = gg[HH + tid];       bi = gb[HH + tid];
        gq = gg[2 * HH + tid];   bq = gb[2 * HH + tid];
        go = gg[3 * HH + tid];   bo = gb[3 * HH + tid];
        cga = cgam[tid];         cbe = cbet[tid];
        creg = g_c0[b * HH + tid];
    }
    float hlast = 0.f;

    // xw prefetch (kc==0 blocks fold xw into their partial)
    float2 xwA = make_float2(0.f, 0.f), xwB = xwA;
    if (kc == 0) {
        xwA = __ldcg((const float2*)&g_xw[(size_t)p1_r * GG + p1_c]);
        xwB = __ldcg((const float2*)&g_xw[(size_t)(p1_r + 8) * GG + p1_c]);
    }

    for (int t = 0; t < TT; t++) {
        // ----- phase 1: load h tile (64 x 256 hi/lo) -----
        // 8 threads/row x 32 halfwords (4 uint4) each
        {
            int r = tid >> 3;                 // 0..63
            int seg = (tid & 7) * 32;
            const uint4* s = (const uint4*)&g_hhi[r * HH + k0 + seg];
            uint4* d = (uint4*)&Ahs[r * WST + seg];
            d[0] = __ldcg(s + 0); d[1] = __ldcg(s + 1);
            d[2] = __ldcg(s + 2); d[3] = __ldcg(s + 3);
            s = (const uint4*)&g_hlo[r * HH + k0 + seg];
            d = (uint4*)&Als[r * WST + seg];
            d[0] = __ldcg(s + 0); d[1] = __ldcg(s + 1);
            d[2] = __ldcg(s + 2); d[3] = __ldcg(s + 3);
        }
        __syncthreads();

        float acc[4] = {0.f, 0.f, 0.f, 0.f};

        const __nv_bfloat16* Abase_h = &Ahs[(wm * 16 + a_row_off) * WST + a_col_off];
        const __nv_bfloat16* Abase_l = &Als[(wm * 16 + a_row_off) * WST + a_col_off];
        const __nv_bfloat16* Bbase_h = &Whs[(wn * 8 + b_row_off) * WST + b_col_off];
        const __nv_bfloat16* Bbase_l = &Wls[(wn * 8 + b_row_off) * WST + b_col_off];

#pragma unroll 8
        for (int ks = 0; ks < 256; ks += 16) {
            unsigned ah[4], al[4], bh[2], bl[2];
            ldsm_x4(ah, Abase_h + ks);
            ldsm_x4(al, Abase_l + ks);
            ldsm_x2(bh, Bbase_h + ks);
            ldsm_x2(bl, Bbase_l + ks);
            mma_bf16(acc, ah, bh);
            mma_bf16(acc, al, bh);
            mma_bf16(acc, ah, bl);
        }

        // store partial (+ xw for kc==0)
        {
            float2 v;
            v.x = acc[0] + xwA.x; v.y = acc[1] + xwA.y;
            *(float2*)&g_part[((size_t)kc * BB + p1_r) * GG + p1_c] = v;
            v.x = acc[2] + xwB.x; v.y = acc[3] + xwB.y;
            *(float2*)&g_part[((size_t)kc * BB + p1_r + 8) * GG + p1_c] = v;
        }

        unsigned valA = 2u * t + 1u;
        unsigned valB = 2u * t + 2u;
        bar_arrive(blk, valA);

        if (writer) {
            bar_wait_all(valA);

            // ----- phase 2: batch row b, one gate element per thread -----
            const float* p0 = g_part + (size_t)b * GG;
            const float* p1 = g_part + (size_t)(BB + b) * GG;
            float vf = __ldcg(&p0[tid])          + __ldcg(&p1[tid]);
            float vi = __ldcg(&p0[HH + tid])     + __ldcg(&p1[HH + tid]);
            float vq = __ldcg(&p0[2 * HH + tid]) + __ldcg(&p1[2 * HH + tid]);
            float vo = __ldcg(&p0[3 * HH + tid]) + __ldcg(&p1[3 * HH + tid]);

            float s = vf + vi + vq + vo;
            float sq = vf * vf + vi * vi + vq * vq + vo * vo;
            block_reduce2(s, sq, red);
            float mean = s * (1.f / GG);
            float var = sq * (1.f / GG) - mean * mean;
            float rstd = rsqrtf(var + EPSV);

            float f = fast_sig((vf - mean) * rstd * gf + bf);
            float i = fast_sig((vi - mean) * rstd * gi + bi);
            float q = fast_tanh((vq - mean) * rstd * gq + bq);
            float o = fast_sig((vo - mean) * rstd * go + bo);
            float c = f * creg + i * q;

            float s2 = c, sq2 = c * c;
            block_reduce2(s2, sq2, red);
            float mean2 = s2 * (1.f / HH);
            float var2 = sq2 * (1.f / HH) - mean2 * mean2;
            float rstd2 = rsqrtf(var2 + EPSV);

            float cn = (c - mean2) * rstd2 * cga + cbe;
            float hn = o * fast_tanh(cn);
            creg = cn;
            hlast = hn;

            __nv_bfloat16 hi, lo;
            split2(hn, hi, lo);
            g_hhi[b * HH + tid] = hi;
            g_hlo[b * HH + tid] = lo;
            out[((size_t)t * BB + b) * HH + tid] = hn;

            bar_arrive(blk, valB);
        }

        // prefetch next step's xw while waiting (kc==0 only)
        if (kc == 0 && t + 1 < TT) {
            size_t tb = (size_t)(t + 1) * BB;
            xwA = __ldcg((const float2*)&g_xw[(tb + p1_r) * GG + p1_c]);
            xwB = __ldcg((const float2*)&g_xw[(tb + p1_r + 8) * GG + p1_c]);
        }

        bar_wait_writers(valB);
    }

    if (writer) {
        out[OUT_HC_OFF + b * HH + tid] = hlast;
        out[OUT_HC_OFF + BB * HH + b * HH + tid] = creg;
    }
}

// ---------------------------------------------------------------------------
extern "C" void kernel_launch(void* const* d_in, const int* in_sizes, int n_in,
                              void* d_out, int out_size) {
    const float* x    = (const float*)d_in[0];
    const float* h0   = (const float*)d_in[1];
    const float* c0   = (const float*)d_in[2];
    const float* w    = (const float*)d_in[3];
    const float* bias = (const float*)d_in[4];
    const float* gg   = (const float*)d_in[5];
    const float* gb   = (const float*)d_in[6];
    const float* cg   = (const float*)d_in[7];
    const float* cb   = (const float*)d_in[8];
    float* out = (float*)d_out;

    // smem: (32+32+64+64) rows * WST halfwords * 2B + reduction scratch
    const int smem_bytes = 192 * WST * 2 + 256;

    static bool attr_set = false;
    if (!attr_set) {
        cudaFuncSetAttribute(lstm_persist,
                             cudaFuncAttributeMaxDynamicSharedMemorySize, smem_bytes);
        attr_set = true;
    }

    init_kernel<<<128, 256>>>(h0, c0);
    split_w_kernel<<<(KK * GG + 255) / 256, 256>>>(w);
    split_x_kernel<<<(int)(((size_t)MM * DD + 255) / 256), 256>>>(x);

    // XW = X @ Wx + bias : M=65536, N=2048, K=512
    gemm_x_kernel<<<dim3(GG / 128, MM / 128), 256>>>(bias);

    // persistent recurrence: all 1024 steps in one launch
    lstm_persist<<<NBLK, THR, smem_bytes>>>(gg, gb, cg, cb, out);
}